// round 11
// baseline (speedup 1.0000x reference)
#include <cuda_runtime.h>
#include <cuda_fp16.h>
#include <cstdint>

#define B_   4
#define N_   50000
#define F_   64
#define E_   800000
#define ROWS_TOTAL (B_ * N_)          // 200000
#define E2_  (2 * E_)                 // 1600000
#define N2_  (2 * N_)                 // 100000
#define SCAN_THREADS 1024
#define SCAN_CHUNK   104              // ints per thread (26 int4)
#define N2P_ (SCAN_THREADS * SCAN_CHUNK)   // 106496 >= N2_

// ---------------------------------------------------------------------------
// Static device scratch (R3 layout)
// ---------------------------------------------------------------------------
// pre-activations in fp16, [support][b*N+n][32 half2]  (51.2 MB total)
__device__ __half2 g_preh[2ull * ROWS_TOTAL * 32];
__device__ int     g_count[N2P_];     // per (support,row) degree (padded)
__device__ int     g_cursor[N2P_];    // fill cursors (= offs after scan)
__device__ int     g_offs[N2P_];      // exclusive prefix (CSR row offsets)
__device__ int     g_csr_col[E2_];
__device__ float   g_csr_val[E2_];

// ---------------------------------------------------------------------------
// zero counters (count only — cursor is written by the scan)
// ---------------------------------------------------------------------------
__global__ void zero_kernel() {
    int i = blockIdx.x * blockDim.x + threadIdx.x;
    if (i < N2P_ / 4) ((int4*)g_count)[i] = make_int4(0, 0, 0, 0);
}

// ---------------------------------------------------------------------------
// histogram of destination rows, both supports (R3 verbatim)
// ---------------------------------------------------------------------------
__global__ __launch_bounds__(256) void hist_kernel(const int* __restrict__ rows1,
                                                   const int* __restrict__ rows2) {
    int t = blockIdx.x * blockDim.x + threadIdx.x;
    if (t >= E2_) return;
    int r = (t < E_) ? __ldg(rows1 + t) : __ldg(rows2 + (t - E_));
    int idx = (t < E_) ? r : (N_ + r);
    atomicAdd(&g_count[idx], 1);
}

// ---------------------------------------------------------------------------
// Single-block exclusive scan of g_count -> g_offs AND g_cursor.
// 1024 threads, 26 int4 per thread; ~800KB L2-resident, two passes.
// ---------------------------------------------------------------------------
__global__ __launch_bounds__(SCAN_THREADS) void scan_kernel() {
    __shared__ int sm[SCAN_THREADS];
    int t = threadIdx.x;
    const int4* cnt4 = (const int4*)g_count;

    int s = 0;
#pragma unroll
    for (int j = 0; j < SCAN_CHUNK / 4; j++) {
        int4 v = cnt4[t * (SCAN_CHUNK / 4) + j];
        s += v.x + v.y + v.z + v.w;
    }
    sm[t] = s;
    __syncthreads();
#pragma unroll
    for (int off = 1; off < SCAN_THREADS; off <<= 1) {
        int add = (t >= off) ? sm[t - off] : 0;
        __syncthreads();
        sm[t] += add;
        __syncthreads();
    }
    int run = sm[t] - s;   // exclusive prefix for this thread

    int4* offs4 = (int4*)g_offs;
    int4* curs4 = (int4*)g_cursor;
#pragma unroll
    for (int j = 0; j < SCAN_CHUNK / 4; j++) {
        int4 v = cnt4[t * (SCAN_CHUNK / 4) + j];
        int4 o;
        o.x = run;
        o.y = o.x + v.x;
        o.z = o.y + v.y;
        o.w = o.z + v.z;
        run  = o.w + v.w;
        offs4[t * (SCAN_CHUNK / 4) + j] = o;
        curs4[t * (SCAN_CHUNK / 4) + j] = o;
    }
}

// ---------------------------------------------------------------------------
// scatter edges into CSR slots. Cursor starts at offs -> one atomic gives
// the absolute slot (no g_offs load). Arrays separate (R3-proven for gather).
// ---------------------------------------------------------------------------
__global__ __launch_bounds__(256) void fill_kernel(const int* __restrict__ rows1,
                                                   const int* __restrict__ cols1,
                                                   const float* __restrict__ vals1,
                                                   const int* __restrict__ rows2,
                                                   const int* __restrict__ cols2,
                                                   const float* __restrict__ vals2) {
    int t = blockIdx.x * blockDim.x + threadIdx.x;
    if (t >= E2_) return;
    int r, c; float v; int idx;
    if (t < E_) {
        r = __ldg(rows1 + t); c = __ldg(cols1 + t); v = __ldg(vals1 + t);
        idx = r;
    } else {
        int e = t - E_;
        r = __ldg(rows2 + e); c = __ldg(cols2 + e); v = __ldg(vals2 + e);
        idx = N_ + r;
    }
    int slot = atomicAdd(&g_cursor[idx], 1);
    g_csr_col[slot] = c;
    g_csr_val[slot] = v;
}

// ---------------------------------------------------------------------------
// fp16 tensor-core GEMM (R9 verbatim). pre1 = x@W1, pre2 = x@W2.
// ---------------------------------------------------------------------------
__global__ __launch_bounds__(256) void gemm_kernel(const float* __restrict__ x,
                                                   const float* __restrict__ W1,
                                                   const float* __restrict__ W2) {
    __shared__ __align__(16) __half xh[64][72];      // [row][k], pad 72
    __shared__ __align__(16) __half Wt[2][64][72];   // [sup][n][k]

    int tid = threadIdx.x;
    int row0 = blockIdx.x * 64;

    for (int i = tid; i < 64 * 64; i += 256) {
        int n = i & 63, k = i >> 6;
        Wt[0][n][k] = __float2half(W1[k * 64 + n]);
        Wt[1][n][k] = __float2half(W2[k * 64 + n]);
    }
    const float4* xg = (const float4*)(x + (size_t)row0 * F_);
    for (int i = tid; i < 1024; i += 256) {          // 64 rows x 16 float4
        float4 v = xg[i];
        int r = i >> 4, kc = (i & 15) * 4;
        xh[r][kc]     = __float2half(v.x);
        xh[r][kc + 1] = __float2half(v.y);
        xh[r][kc + 2] = __float2half(v.z);
        xh[r][kc + 3] = __float2half(v.w);
    }
    __syncthreads();

    int wid  = tid >> 5, lane = tid & 31;
    int sup  = wid >> 2;
    int m0   = (wid & 3) * 16;
    int g    = lane >> 2;
    int tg   = lane & 3;

    float acc[8][4];
#pragma unroll
    for (int n = 0; n < 8; n++)
#pragma unroll
        for (int j = 0; j < 4; j++) acc[n][j] = 0.f;

#pragma unroll
    for (int ks = 0; ks < 4; ks++) {
        int kb = ks * 16 + tg * 2;
        uint32_t a0 = *(const uint32_t*)&xh[m0 + g][kb];
        uint32_t a1 = *(const uint32_t*)&xh[m0 + g + 8][kb];
        uint32_t a2 = *(const uint32_t*)&xh[m0 + g][kb + 8];
        uint32_t a3 = *(const uint32_t*)&xh[m0 + g + 8][kb + 8];
#pragma unroll
        for (int n = 0; n < 8; n++) {
            uint32_t b0 = *(const uint32_t*)&Wt[sup][n * 8 + g][kb];
            uint32_t b1 = *(const uint32_t*)&Wt[sup][n * 8 + g][kb + 8];
            asm volatile(
                "mma.sync.aligned.m16n8k16.row.col.f32.f16.f16.f32 "
                "{%0,%1,%2,%3}, {%4,%5,%6,%7}, {%8,%9}, {%0,%1,%2,%3};"
                : "+f"(acc[n][0]), "+f"(acc[n][1]), "+f"(acc[n][2]), "+f"(acc[n][3])
                : "r"(a0), "r"(a1), "r"(a2), "r"(a3), "r"(b0), "r"(b1));
        }
    }

    const size_t sup_stride = (size_t)ROWS_TOTAL * 32;
    __half2* dst = g_preh + (size_t)sup * sup_stride;
#pragma unroll
    for (int n = 0; n < 8; n++) {
        int fpair = n * 4 + tg;
        size_t r = (size_t)(row0 + m0 + g);
        dst[r * 32 + fpair]       = __floats2half2_rn(acc[n][0], acc[n][1]);
        dst[(r + 8) * 32 + fpair] = __floats2half2_rn(acc[n][2], acc[n][3]);
    }
}

// ---------------------------------------------------------------------------
// Gather SpMM + bias + relu (R3 verbatim). One warp per row, all 4 batches.
// ---------------------------------------------------------------------------
__global__ __launch_bounds__(256) void gather_kernel(const float* __restrict__ bias,
                                                     float* __restrict__ out) {
    int gw   = (blockIdx.x * blockDim.x + threadIdx.x) >> 5;
    int lane = threadIdx.x & 31;
    if (gw >= N_) return;
    int row = gw;

    float bx = __ldg(bias + lane * 2);
    float by = __ldg(bias + lane * 2 + 1);
    float2 acc[4];
#pragma unroll
    for (int b = 0; b < 4; b++) acc[b] = make_float2(bx, by);

    const size_t sup_stride = (size_t)ROWS_TOTAL * 32;
    const size_t bstride    = (size_t)N_ * 32;

#pragma unroll
    for (int s = 0; s < 2; s++) {
        int idx   = s * N_ + row;
        int start = g_offs[idx];
        int deg   = g_count[idx];
        const __half2* pre = g_preh + (size_t)s * sup_stride;

        for (int c0 = 0; c0 < deg; c0 += 32) {
            int nc = min(32, deg - c0);
            int   colv = 0;
            float vv   = 0.f;
            if (lane < nc) {
                colv = g_csr_col[start + c0 + lane];
                vv   = g_csr_val[start + c0 + lane];
            }
            for (int i = 0; i < nc; i++) {
                int   ci = __shfl_sync(0xffffffffu, colv, i);
                float vi = __shfl_sync(0xffffffffu, vv,   i);
                const __half2* src = pre + (size_t)ci * 32 + lane;
#pragma unroll
                for (int b = 0; b < 4; b++) {
                    __half2 h = __ldg(src + (size_t)b * bstride);
                    float2 f = __half22float2(h);
                    acc[b].x = fmaf(vi, f.x, acc[b].x);
                    acc[b].y = fmaf(vi, f.y, acc[b].y);
                }
            }
        }
    }

    float2* outv = (float2*)out;
#pragma unroll
    for (int b = 0; b < 4; b++) {
        float2 o;
        o.x = fmaxf(acc[b].x, 0.f);
        o.y = fmaxf(acc[b].y, 0.f);
        outv[((size_t)b * N_ + row) * 32 + lane] = o;
    }
}

extern "C" void kernel_launch(void* const* d_in, const int* in_sizes, int n_in,
                              void* d_out, int out_size) {
    const float* x     = (const float*)d_in[0];
    const int*   rows1 = (const int*)  d_in[1];
    const int*   cols1 = (const int*)  d_in[2];
    const float* vals1 = (const float*)d_in[3];
    const int*   rows2 = (const int*)  d_in[4];
    const int*   cols2 = (const int*)  d_in[5];
    const float* vals2 = (const float*)d_in[6];
    const float* W1    = (const float*)d_in[7];
    const float* W2    = (const float*)d_in[8];
    const float* bias  = (const float*)d_in[9];
    float*       out   = (float*)d_out;

    // Lazily-created side stream + events (first call is the eager
    // correctness run — never during graph capture).
    static cudaStream_t s_side = nullptr;
    static cudaEvent_t  ev_fork = nullptr;
    static cudaEvent_t  ev_join = nullptr;
    if (s_side == nullptr) {
        cudaStreamCreateWithFlags(&s_side, cudaStreamNonBlocking);
        cudaEventCreateWithFlags(&ev_fork, cudaEventDisableTiming);
        cudaEventCreateWithFlags(&ev_join, cudaEventDisableTiming);
    }

    // ---- fork: gemm runs concurrently with the CSR build ----
    cudaEventRecord(ev_fork, 0);
    cudaStreamWaitEvent(s_side, ev_fork, 0);
    gemm_kernel<<<ROWS_TOTAL / 64, 256, 0, s_side>>>(x, W1, W2);
    cudaEventRecord(ev_join, s_side);

    // ---- main chain: CSR construction ----
    zero_kernel<<<(N2P_ / 4 + 255) / 256, 256>>>();
    hist_kernel<<<(E2_ + 255) / 256, 256>>>(rows1, rows2);
    scan_kernel<<<1, SCAN_THREADS>>>();
    fill_kernel<<<(E2_ + 255) / 256, 256>>>(rows1, cols1, vals1, rows2, cols2, vals2);

    // ---- join: gather needs both pre-activations and the CSR ----
    cudaStreamWaitEvent(0, ev_join, 0);
    gather_kernel<<<(N_ * 32 + 255) / 256, 256>>>(bias, out);
}

// round 12
// speedup vs baseline: 1.4178x; 1.4178x over previous
#include <cuda_runtime.h>
#include <cuda_fp16.h>
#include <cstdint>

#define B_   4
#define N_   50000
#define F_   64
#define E_   800000
#define ROWS_TOTAL (B_ * N_)          // 200000
#define E2_  (2 * E_)                 // 1600000
#define N2_  (2 * N_)                 // 100000

// ---------------------------------------------------------------------------
// Static device scratch
// ---------------------------------------------------------------------------
// pre-activations fp16, layout [support][node][batch][64 half]  (51.2 MB)
__device__ __half2 g_preh[2ull * N_ * B_ * 32];
__device__ int     g_count[N2_];      // per (support,row) degree
__device__ int     g_cursor[N2_];     // fill cursors
__device__ int     g_offs[N2_];       // exclusive prefix (CSR row offsets)
__device__ int     g_btot[128];       // scan block totals
__device__ int2    g_csr_cv[E2_];     // packed (col, val-bits)

// ---------------------------------------------------------------------------
// zero counters (R10 verbatim)
// ---------------------------------------------------------------------------
__global__ void zero_kernel() {
    int i = blockIdx.x * blockDim.x + threadIdx.x;
    if (i < N2_) { g_count[i] = 0; g_cursor[i] = 0; }
}

// ---------------------------------------------------------------------------
// histogram of destination rows, both supports (R10 verbatim)
// ---------------------------------------------------------------------------
__global__ __launch_bounds__(256) void hist_kernel(const int* __restrict__ rows1,
                                                   const int* __restrict__ rows2) {
    int t = blockIdx.x * blockDim.x + threadIdx.x;
    if (t >= E2_) return;
    int r = (t < E_) ? __ldg(rows1 + t) : __ldg(rows2 + (t - E_));
    int idx = (t < E_) ? r : (N_ + r);
    atomicAdd(&g_count[idx], 1);
}

// ---------------------------------------------------------------------------
// exclusive scan of g_count (100000 ints) -> g_offs, 2-level (R10 verbatim)
// ---------------------------------------------------------------------------
__global__ __launch_bounds__(256) void scan_blocks_kernel() {
    __shared__ int sm[256];
    int base = blockIdx.x * 1024 + threadIdx.x * 4;
    int v[4];
#pragma unroll
    for (int j = 0; j < 4; j++) v[j] = (base + j < N2_) ? g_count[base + j] : 0;
    int t = v[0] + v[1] + v[2] + v[3];
    sm[threadIdx.x] = t;
    __syncthreads();
#pragma unroll
    for (int off = 1; off < 256; off <<= 1) {
        int add = (threadIdx.x >= off) ? sm[threadIdx.x - off] : 0;
        __syncthreads();
        sm[threadIdx.x] += add;
        __syncthreads();
    }
    int run = sm[threadIdx.x] - t;
#pragma unroll
    for (int j = 0; j < 4; j++) {
        if (base + j < N2_) g_offs[base + j] = run;
        run += v[j];
    }
    if (threadIdx.x == 255) g_btot[blockIdx.x] = sm[255];
}

__global__ void scan_tops_kernel(int nblk) {
    __shared__ int sm[128];
    int t = (threadIdx.x < nblk) ? g_btot[threadIdx.x] : 0;
    sm[threadIdx.x] = t;
    __syncthreads();
#pragma unroll
    for (int off = 1; off < 128; off <<= 1) {
        int add = (threadIdx.x >= off) ? sm[threadIdx.x - off] : 0;
        __syncthreads();
        sm[threadIdx.x] += add;
        __syncthreads();
    }
    if (threadIdx.x < nblk) g_btot[threadIdx.x] = sm[threadIdx.x] - t;
}

__global__ void scan_apply_kernel() {
    int i = blockIdx.x * blockDim.x + threadIdx.x;
    if (i < N2_) g_offs[i] += g_btot[i >> 10];
}

// ---------------------------------------------------------------------------
// scatter edges into CSR slots (packed col+val, one STG.64)
// ---------------------------------------------------------------------------
__global__ __launch_bounds__(256) void fill_kernel(const int* __restrict__ rows1,
                                                   const int* __restrict__ cols1,
                                                   const float* __restrict__ vals1,
                                                   const int* __restrict__ rows2,
                                                   const int* __restrict__ cols2,
                                                   const float* __restrict__ vals2) {
    int t = blockIdx.x * blockDim.x + threadIdx.x;
    if (t >= E2_) return;
    int c; float v; int idx;
    if (t < E_) {
        idx = __ldg(rows1 + t);
        c   = __ldg(cols1 + t);
        v   = __ldg(vals1 + t);
    } else {
        int e = t - E_;
        idx = N_ + __ldg(rows2 + e);
        c   = __ldg(cols2 + e);
        v   = __ldg(vals2 + e);
    }
    int slot = g_offs[idx] + atomicAdd(&g_cursor[idx], 1);
    g_csr_cv[slot] = make_int2(c, __float_as_int(v));
}

// ---------------------------------------------------------------------------
// fp16 tensor-core GEMM (R9 body; epilogue targets [sup][node][batch] layout).
// ---------------------------------------------------------------------------
__global__ __launch_bounds__(256) void gemm_kernel(const float* __restrict__ x,
                                                   const float* __restrict__ W1,
                                                   const float* __restrict__ W2) {
    __shared__ __align__(16) __half xh[64][72];      // [row][k], pad 72
    __shared__ __align__(16) __half Wt[2][64][72];   // [sup][n][k]

    int tid = threadIdx.x;
    int row0 = blockIdx.x * 64;

    for (int i = tid; i < 64 * 64; i += 256) {
        int n = i & 63, k = i >> 6;
        Wt[0][n][k] = __float2half(W1[k * 64 + n]);
        Wt[1][n][k] = __float2half(W2[k * 64 + n]);
    }
    const float4* xg = (const float4*)(x + (size_t)row0 * F_);
    for (int i = tid; i < 1024; i += 256) {          // 64 rows x 16 float4
        float4 v = xg[i];
        int r = i >> 4, kc = (i & 15) * 4;
        xh[r][kc]     = __float2half(v.x);
        xh[r][kc + 1] = __float2half(v.y);
        xh[r][kc + 2] = __float2half(v.z);
        xh[r][kc + 3] = __float2half(v.w);
    }
    __syncthreads();

    int wid  = tid >> 5, lane = tid & 31;
    int sup  = wid >> 2;
    int m0   = (wid & 3) * 16;
    int g    = lane >> 2;
    int tg   = lane & 3;

    float acc[8][4];
#pragma unroll
    for (int n = 0; n < 8; n++)
#pragma unroll
        for (int j = 0; j < 4; j++) acc[n][j] = 0.f;

#pragma unroll
    for (int ks = 0; ks < 4; ks++) {
        int kb = ks * 16 + tg * 2;
        uint32_t a0 = *(const uint32_t*)&xh[m0 + g][kb];
        uint32_t a1 = *(const uint32_t*)&xh[m0 + g + 8][kb];
        uint32_t a2 = *(const uint32_t*)&xh[m0 + g][kb + 8];
        uint32_t a3 = *(const uint32_t*)&xh[m0 + g + 8][kb + 8];
#pragma unroll
        for (int n = 0; n < 8; n++) {
            uint32_t b0 = *(const uint32_t*)&Wt[sup][n * 8 + g][kb];
            uint32_t b1 = *(const uint32_t*)&Wt[sup][n * 8 + g][kb + 8];
            asm volatile(
                "mma.sync.aligned.m16n8k16.row.col.f32.f16.f16.f32 "
                "{%0,%1,%2,%3}, {%4,%5,%6,%7}, {%8,%9}, {%0,%1,%2,%3};"
                : "+f"(acc[n][0]), "+f"(acc[n][1]), "+f"(acc[n][2]), "+f"(acc[n][3])
                : "r"(a0), "r"(a1), "r"(a2), "r"(a3), "r"(b0), "r"(b1));
        }
    }

    // epilogue into [sup][node][batch][32 half2]
    const size_t sup_stride = (size_t)N_ * B_ * 32;   // half2 units
    __half2* dst = g_preh + (size_t)sup * sup_stride;
#pragma unroll
    for (int n = 0; n < 8; n++) {
        int fpair = n * 4 + tg;
#pragma unroll
        for (int h = 0; h < 2; h++) {
            int flat = row0 + m0 + g + h * 8;      // flattened b*N + node
            int b    = flat / N_;
            int node = flat - b * N_;
            size_t base = ((size_t)node * B_ + b) * 32;
            dst[base + fpair] = __floats2half2_rn(acc[n][2 * h], acc[n][2 * h + 1]);
        }
    }
}

// ---------------------------------------------------------------------------
// Gather SpMM + bias + relu. One warp per row, all 4 batches.
// Lane l = (batch = l>>3, chunk fo = l&7): one LDG.128 per edge covers the
// whole 512B node block. Each lane: 8 features of one batch, fp32 acc.
// ---------------------------------------------------------------------------
__global__ __launch_bounds__(256) void gather_kernel(const float* __restrict__ bias,
                                                     float* __restrict__ out) {
    int row  = (blockIdx.x * blockDim.x + threadIdx.x) >> 5;
    int lane = threadIdx.x & 31;
    if (row >= N_) return;
    int b  = lane >> 3;
    int fo = lane & 7;          // 8-feature chunk

    float acc[8];
#pragma unroll
    for (int j = 0; j < 8; j++) acc[j] = __ldg(bias + fo * 8 + j);

    const size_t sup_stride_u4 = (size_t)N_ * B_ * 8;   // uint4 units

#pragma unroll
    for (int s = 0; s < 2; s++) {
        int idx   = s * N_ + row;
        int start = g_offs[idx];
        int deg   = g_count[idx];
        const uint4* pre = (const uint4*)g_preh + (size_t)s * sup_stride_u4 + lane;

        for (int c0 = 0; c0 < deg; c0 += 32) {
            int nc = min(32, deg - c0);
            int2 cv = make_int2(0, 0);
            if (lane < nc) cv = __ldg(g_csr_cv + start + c0 + lane);
            for (int i = 0; i < nc; i++) {
                int   ci = __shfl_sync(0xffffffffu, cv.x, i);
                float vi = __int_as_float(__shfl_sync(0xffffffffu, cv.y, i));
                uint4 h  = __ldg(pre + (size_t)ci * 32);   // 32 uint4 per node
                float2 f0 = __half22float2(*(const __half2*)&h.x);
                float2 f1 = __half22float2(*(const __half2*)&h.y);
                float2 f2 = __half22float2(*(const __half2*)&h.z);
                float2 f3 = __half22float2(*(const __half2*)&h.w);
                acc[0] = fmaf(vi, f0.x, acc[0]);
                acc[1] = fmaf(vi, f0.y, acc[1]);
                acc[2] = fmaf(vi, f1.x, acc[2]);
                acc[3] = fmaf(vi, f1.y, acc[3]);
                acc[4] = fmaf(vi, f2.x, acc[4]);
                acc[5] = fmaf(vi, f2.y, acc[5]);
                acc[6] = fmaf(vi, f3.x, acc[6]);
                acc[7] = fmaf(vi, f3.y, acc[7]);
            }
        }
    }

    float4* outv = (float4*)(out + ((size_t)b * N_ + row) * F_ + fo * 8);
    float4 o0, o1;
    o0.x = fmaxf(acc[0], 0.f); o0.y = fmaxf(acc[1], 0.f);
    o0.z = fmaxf(acc[2], 0.f); o0.w = fmaxf(acc[3], 0.f);
    o1.x = fmaxf(acc[4], 0.f); o1.y = fmaxf(acc[5], 0.f);
    o1.z = fmaxf(acc[6], 0.f); o1.w = fmaxf(acc[7], 0.f);
    outv[0] = o0;
    outv[1] = o1;
}

extern "C" void kernel_launch(void* const* d_in, const int* in_sizes, int n_in,
                              void* d_out, int out_size) {
    const float* x     = (const float*)d_in[0];
    const int*   rows1 = (const int*)  d_in[1];
    const int*   cols1 = (const int*)  d_in[2];
    const float* vals1 = (const float*)d_in[3];
    const int*   rows2 = (const int*)  d_in[4];
    const int*   cols2 = (const int*)  d_in[5];
    const float* vals2 = (const float*)d_in[6];
    const float* W1    = (const float*)d_in[7];
    const float* W2    = (const float*)d_in[8];
    const float* bias  = (const float*)d_in[9];
    float*       out   = (float*)d_out;

    static cudaStream_t s_side = nullptr;
    static cudaEvent_t  ev_fork = nullptr;
    static cudaEvent_t  ev_join = nullptr;
    if (s_side == nullptr) {
        cudaStreamCreateWithFlags(&s_side, cudaStreamNonBlocking);
        cudaEventCreateWithFlags(&ev_fork, cudaEventDisableTiming);
        cudaEventCreateWithFlags(&ev_join, cudaEventDisableTiming);
    }

    const int nScanBlocks = (N2_ + 1023) / 1024;   // 98

    // ---- fork: gemm runs concurrently with the CSR build ----
    cudaEventRecord(ev_fork, 0);
    cudaStreamWaitEvent(s_side, ev_fork, 0);
    gemm_kernel<<<ROWS_TOTAL / 64, 256, 0, s_side>>>(x, W1, W2);
    cudaEventRecord(ev_join, s_side);

    // ---- main chain: CSR construction (3-kernel scan, R10 verbatim) ----
    zero_kernel<<<(N2_ + 255) / 256, 256>>>();
    hist_kernel<<<(E2_ + 255) / 256, 256>>>(rows1, rows2);
    scan_blocks_kernel<<<nScanBlocks, 256>>>();
    scan_tops_kernel<<<1, 128>>>(nScanBlocks);
    scan_apply_kernel<<<(N2_ + 255) / 256, 256>>>();
    fill_kernel<<<(E2_ + 255) / 256, 256>>>(rows1, cols1, vals1, rows2, cols2, vals2);

    // ---- join: gather needs both pre-activations and the CSR ----
    cudaStreamWaitEvent(0, ev_join, 0);
    gather_kernel<<<(N_ * 32 + 255) / 256, 256>>>(bias, out);
}

// round 13
// speedup vs baseline: 1.4478x; 1.0212x over previous
#include <cuda_runtime.h>
#include <cuda_fp16.h>
#include <cstdint>

#define B_   4
#define N_   50000
#define F_   64
#define E_   800000
#define ROWS_TOTAL (B_ * N_)          // 200000
#define E2_  (2 * E_)                 // 1600000
#define N2_  (2 * N_)                 // 100000
#define SCAN_BLOCKS ((N2_ + 1023) / 1024)   // 98

// ---------------------------------------------------------------------------
// Static device scratch
// ---------------------------------------------------------------------------
// pre-activations fp16, layout [support][node][batch][64 half]  (51.2 MB)
__device__ __half2 g_preh[2ull * N_ * B_ * 32];
__device__ int     g_count[N2_];      // per (support,row) degree
__device__ int     g_cursor[N2_];     // fill cursors (= offs after scan)
__device__ int     g_offs[N2_];       // exclusive prefix (CSR row offsets)
__device__ unsigned long long g_partials[SCAN_BLOCKS];  // (flag<<32)|sum
__device__ int2    g_csr_cv[E2_];     // packed (col, val-bits)

// ---------------------------------------------------------------------------
// zero counters + lookback state (cursor is written by the scan)
// ---------------------------------------------------------------------------
__global__ void zero_kernel() {
    int i = blockIdx.x * blockDim.x + threadIdx.x;
    if (i < N2_) g_count[i] = 0;
    if (i < SCAN_BLOCKS) g_partials[i] = 0ull;
}

// ---------------------------------------------------------------------------
// histogram of destination rows, both supports (R12 verbatim)
// ---------------------------------------------------------------------------
__global__ __launch_bounds__(256) void hist_kernel(const int* __restrict__ rows1,
                                                   const int* __restrict__ rows2) {
    int t = blockIdx.x * blockDim.x + threadIdx.x;
    if (t >= E2_) return;
    int r = (t < E_) ? __ldg(rows1 + t) : __ldg(rows2 + (t - E_));
    int idx = (t < E_) ? r : (N_ + r);
    atomicAdd(&g_count[idx], 1);
}

// ---------------------------------------------------------------------------
// Single-kernel decoupled-lookback exclusive scan of g_count
// -> g_offs AND g_cursor.  98 blocks x 256 threads, 4 ints/thread.
// flag: 1 = aggregate available, 2 = inclusive prefix available.
// ---------------------------------------------------------------------------
__global__ __launch_bounds__(256) void scan_kernel() {
    __shared__ int sm[256];
    __shared__ int sm_excl;
    int bid = blockIdx.x;
    int tid = threadIdx.x;
    int lane = tid & 31;
    int base = bid * 1024 + tid * 4;

    int v[4];
#pragma unroll
    for (int j = 0; j < 4; j++) v[j] = (base + j < N2_) ? g_count[base + j] : 0;
    int s = v[0] + v[1] + v[2] + v[3];
    sm[tid] = s;
    __syncthreads();
#pragma unroll
    for (int off = 1; off < 256; off <<= 1) {
        int add = (tid >= off) ? sm[tid - off] : 0;
        __syncthreads();
        sm[tid] += add;
        __syncthreads();
    }
    int run   = sm[tid] - s;      // exclusive thread prefix within block
    int total = sm[255];          // block total

    // publish aggregate (block 0 publishes inclusive immediately)
    if (tid == 0) {
        if (bid == 0) {
            sm_excl = 0;
            atomicExch(&g_partials[0], (2ull << 32) | (unsigned)total);
        } else {
            atomicExch(&g_partials[bid], (1ull << 32) | (unsigned)total);
        }
    }

    // warp 0 lookback (parallel over 32 predecessors per step)
    if (bid > 0 && tid < 32) {
        int running = 0;
        int pbase = bid - 1;
        for (;;) {
            int j = pbase - lane;
            unsigned long long w = 0;
            if (j >= 0) {
                do { w = atomicAdd(&g_partials[j], 0ull); } while ((w >> 32) == 0);
            }
            unsigned inclm = __ballot_sync(0xffffffffu, (j >= 0) && ((w >> 32) == 2));
            int firstIncl = inclm ? (__ffs(inclm) - 1) : 32;
            int val = ((j >= 0) && (lane <= firstIncl)) ? (int)(unsigned)w : 0;
#pragma unroll
            for (int o = 16; o; o >>= 1) val += __shfl_down_sync(0xffffffffu, val, o);
            val = __shfl_sync(0xffffffffu, val, 0);
            running += val;
            if (firstIncl < 32 || pbase - 31 <= -1 + 0) {
                if (firstIncl < 32) break;
            }
            if (firstIncl < 32) break;
            pbase -= 32;
            if (pbase < 0) break;
        }
        if (lane == 0) {
            sm_excl = running;
            atomicExch(&g_partials[bid], (2ull << 32) | (unsigned)(running + total));
        }
    }
    __syncthreads();

    int bexcl = sm_excl;
    run += bexcl;
#pragma unroll
    for (int j = 0; j < 4; j++) {
        if (base + j < N2_) {
            g_offs[base + j]   = run;
            g_cursor[base + j] = run;
        }
        run += v[j];
    }
}

// ---------------------------------------------------------------------------
// scatter edges into CSR slots. cursor starts at offs -> one atomic gives
// the absolute slot (no g_offs load). Packed col+val, one STG.64.
// ---------------------------------------------------------------------------
__global__ __launch_bounds__(256) void fill_kernel(const int* __restrict__ rows1,
                                                   const int* __restrict__ cols1,
                                                   const float* __restrict__ vals1,
                                                   const int* __restrict__ rows2,
                                                   const int* __restrict__ cols2,
                                                   const float* __restrict__ vals2) {
    int t = blockIdx.x * blockDim.x + threadIdx.x;
    if (t >= E2_) return;
    int c; float v; int idx;
    if (t < E_) {
        idx = __ldg(rows1 + t);
        c   = __ldg(cols1 + t);
        v   = __ldg(vals1 + t);
    } else {
        int e = t - E_;
        idx = N_ + __ldg(rows2 + e);
        c   = __ldg(cols2 + e);
        v   = __ldg(vals2 + e);
    }
    int slot = atomicAdd(&g_cursor[idx], 1);
    g_csr_cv[slot] = make_int2(c, __float_as_int(v));
}

// ---------------------------------------------------------------------------
// fp16 tensor-core GEMM (R12 verbatim; epilogue in [sup][node][batch] layout).
// ---------------------------------------------------------------------------
__global__ __launch_bounds__(256) void gemm_kernel(const float* __restrict__ x,
                                                   const float* __restrict__ W1,
                                                   const float* __restrict__ W2) {
    __shared__ __align__(16) __half xh[64][72];      // [row][k], pad 72
    __shared__ __align__(16) __half Wt[2][64][72];   // [sup][n][k]

    int tid = threadIdx.x;
    int row0 = blockIdx.x * 64;

    for (int i = tid; i < 64 * 64; i += 256) {
        int n = i & 63, k = i >> 6;
        Wt[0][n][k] = __float2half(W1[k * 64 + n]);
        Wt[1][n][k] = __float2half(W2[k * 64 + n]);
    }
    const float4* xg = (const float4*)(x + (size_t)row0 * F_);
    for (int i = tid; i < 1024; i += 256) {          // 64 rows x 16 float4
        float4 v = xg[i];
        int r = i >> 4, kc = (i & 15) * 4;
        xh[r][kc]     = __float2half(v.x);
        xh[r][kc + 1] = __float2half(v.y);
        xh[r][kc + 2] = __float2half(v.z);
        xh[r][kc + 3] = __float2half(v.w);
    }
    __syncthreads();

    int wid  = tid >> 5, lane = tid & 31;
    int sup  = wid >> 2;
    int m0   = (wid & 3) * 16;
    int g    = lane >> 2;
    int tg   = lane & 3;

    float acc[8][4];
#pragma unroll
    for (int n = 0; n < 8; n++)
#pragma unroll
        for (int j = 0; j < 4; j++) acc[n][j] = 0.f;

#pragma unroll
    for (int ks = 0; ks < 4; ks++) {
        int kb = ks * 16 + tg * 2;
        uint32_t a0 = *(const uint32_t*)&xh[m0 + g][kb];
        uint32_t a1 = *(const uint32_t*)&xh[m0 + g + 8][kb];
        uint32_t a2 = *(const uint32_t*)&xh[m0 + g][kb + 8];
        uint32_t a3 = *(const uint32_t*)&xh[m0 + g + 8][kb + 8];
#pragma unroll
        for (int n = 0; n < 8; n++) {
            uint32_t b0 = *(const uint32_t*)&Wt[sup][n * 8 + g][kb];
            uint32_t b1 = *(const uint32_t*)&Wt[sup][n * 8 + g][kb + 8];
            asm volatile(
                "mma.sync.aligned.m16n8k16.row.col.f32.f16.f16.f32 "
                "{%0,%1,%2,%3}, {%4,%5,%6,%7}, {%8,%9}, {%0,%1,%2,%3};"
                : "+f"(acc[n][0]), "+f"(acc[n][1]), "+f"(acc[n][2]), "+f"(acc[n][3])
                : "r"(a0), "r"(a1), "r"(a2), "r"(a3), "r"(b0), "r"(b1));
        }
    }

    const size_t sup_stride = (size_t)N_ * B_ * 32;   // half2 units
    __half2* dst = g_preh + (size_t)sup * sup_stride;
#pragma unroll
    for (int n = 0; n < 8; n++) {
        int fpair = n * 4 + tg;
#pragma unroll
        for (int h = 0; h < 2; h++) {
            int flat = row0 + m0 + g + h * 8;      // flattened b*N + node
            int b    = flat / N_;
            int node = flat - b * N_;
            size_t base = ((size_t)node * B_ + b) * 32;
            dst[base + fpair] = __floats2half2_rn(acc[n][2 * h], acc[n][2 * h + 1]);
        }
    }
}

// ---------------------------------------------------------------------------
// Gather SpMM + bias + relu (R12 verbatim). One warp per row, all 4 batches,
// one LDG.128 per edge covering the whole 512B node block.
// ---------------------------------------------------------------------------
__global__ __launch_bounds__(256) void gather_kernel(const float* __restrict__ bias,
                                                     float* __restrict__ out) {
    int row  = (blockIdx.x * blockDim.x + threadIdx.x) >> 5;
    int lane = threadIdx.x & 31;
    if (row >= N_) return;
    int b  = lane >> 3;
    int fo = lane & 7;          // 8-feature chunk

    float acc[8];
#pragma unroll
    for (int j = 0; j < 8; j++) acc[j] = __ldg(bias + fo * 8 + j);

    const size_t sup_stride_u4 = (size_t)N_ * B_ * 8;   // uint4 units

#pragma unroll
    for (int s = 0; s < 2; s++) {
        int idx   = s * N_ + row;
        int start = g_offs[idx];
        int deg   = g_count[idx];
        const uint4* pre = (const uint4*)g_preh + (size_t)s * sup_stride_u4 + lane;

        for (int c0 = 0; c0 < deg; c0 += 32) {
            int nc = min(32, deg - c0);
            int2 cv = make_int2(0, 0);
            if (lane < nc) cv = __ldg(g_csr_cv + start + c0 + lane);
            for (int i = 0; i < nc; i++) {
                int   ci = __shfl_sync(0xffffffffu, cv.x, i);
                float vi = __int_as_float(__shfl_sync(0xffffffffu, cv.y, i));
                uint4 h  = __ldg(pre + (size_t)ci * 32);   // 32 uint4 per node
                float2 f0 = __half22float2(*(const __half2*)&h.x);
                float2 f1 = __half22float2(*(const __half2*)&h.y);
                float2 f2 = __half22float2(*(const __half2*)&h.z);
                float2 f3 = __half22float2(*(const __half2*)&h.w);
                acc[0] = fmaf(vi, f0.x, acc[0]);
                acc[1] = fmaf(vi, f0.y, acc[1]);
                acc[2] = fmaf(vi, f1.x, acc[2]);
                acc[3] = fmaf(vi, f1.y, acc[3]);
                acc[4] = fmaf(vi, f2.x, acc[4]);
                acc[5] = fmaf(vi, f2.y, acc[5]);
                acc[6] = fmaf(vi, f3.x, acc[6]);
                acc[7] = fmaf(vi, f3.y, acc[7]);
            }
        }
    }

    float4* outv = (float4*)(out + ((size_t)b * N_ + row) * F_ + fo * 8);
    float4 o0, o1;
    o0.x = fmaxf(acc[0], 0.f); o0.y = fmaxf(acc[1], 0.f);
    o0.z = fmaxf(acc[2], 0.f); o0.w = fmaxf(acc[3], 0.f);
    o1.x = fmaxf(acc[4], 0.f); o1.y = fmaxf(acc[5], 0.f);
    o1.z = fmaxf(acc[6], 0.f); o1.w = fmaxf(acc[7], 0.f);
    outv[0] = o0;
    outv[1] = o1;
}

extern "C" void kernel_launch(void* const* d_in, const int* in_sizes, int n_in,
                              void* d_out, int out_size) {
    const float* x     = (const float*)d_in[0];
    const int*   rows1 = (const int*)  d_in[1];
    const int*   cols1 = (const int*)  d_in[2];
    const float* vals1 = (const float*)d_in[3];
    const int*   rows2 = (const int*)  d_in[4];
    const int*   cols2 = (const int*)  d_in[5];
    const float* vals2 = (const float*)d_in[6];
    const float* W1    = (const float*)d_in[7];
    const float* W2    = (const float*)d_in[8];
    const float* bias  = (const float*)d_in[9];
    float*       out   = (float*)d_out;

    static cudaStream_t s_side = nullptr;
    static cudaEvent_t  ev_fork = nullptr;
    static cudaEvent_t  ev_join = nullptr;
    if (s_side == nullptr) {
        cudaStreamCreateWithFlags(&s_side, cudaStreamNonBlocking);
        cudaEventCreateWithFlags(&ev_fork, cudaEventDisableTiming);
        cudaEventCreateWithFlags(&ev_join, cudaEventDisableTiming);
    }

    // ---- fork: gemm runs concurrently with the CSR build ----
    cudaEventRecord(ev_fork, 0);
    cudaStreamWaitEvent(s_side, ev_fork, 0);
    gemm_kernel<<<ROWS_TOTAL / 64, 256, 0, s_side>>>(x, W1, W2);
    cudaEventRecord(ev_join, s_side);

    // ---- main chain: CSR construction ----
    zero_kernel<<<(N2_ + 255) / 256, 256>>>();
    hist_kernel<<<(E2_ + 255) / 256, 256>>>(rows1, rows2);
    scan_kernel<<<SCAN_BLOCKS, 256>>>();
    fill_kernel<<<(E2_ + 255) / 256, 256>>>(rows1, cols1, vals1, rows2, cols2, vals2);

    // ---- join: gather needs both pre-activations and the CSR ----
    cudaStreamWaitEvent(0, ev_join, 0);
    gather_kernel<<<(N_ * 32 + 255) / 256, 256>>>(bias, out);
}